// round 15
// baseline (speedup 1.0000x reference)
#include <cuda_runtime.h>
#include <cuda_bf16.h>

// Problem constants (must match reference)
#define NUM_NODES   1200000
#define NUM_PHYS    1000000
#define NUM_MOVABLE 900000
#define NB          512
#define KSTEN       5

// Persistent-kernel shape: 6 CTAs/SM guaranteed by __launch_bounds__(256,6)
// (reg cap 40, smem 0), 148 SMs minimum on sm_103a -> 888 CTAs all resident.
#define TPB        256
#define GRID_CTAS  888
#define NTHREADS   (GRID_CTAS * TPB)

// BSX = BSY = 1000/512 = 1.953125 (exact in fp32)
#define BS 1.953125f

// Compile-time double folds, cast to f32 exactly as JAX weak-type promotion does
__device__ __forceinline__ float stretch_c() { return (float)(1.953125 * 1.4142135623730951); }
__device__ __forceinline__ float cap_denom() { return (float)(1.953125 * 1.953125 * 0.05); }
__device__ __forceinline__ float min_rate()  { return (float)(1.0 / 1.5); }

// Scratch (no allocations allowed). Row-major bin maps, 16B-aligned.
// Zero-init at load; the util phase re-zeroes g_pin_map every run, so
// "pin_map == 0 at scatter entry" holds for correctness call, capture call,
// and every graph replay.
__device__ __align__(16) float g_pin_map[NB * NB];
__device__ __align__(16) float g_util[NB * NB];

// Grid barrier state. Generation counter is monotonic: works identically on
// every graph replay (comparisons are relative), count returns to 0.
__device__ unsigned g_bar_count = 0;
__device__ volatile unsigned g_bar_gen = 0;

__device__ __forceinline__ void grid_sync() {
    __threadfence();                      // publish this thread's prior writes/REDs
    __syncthreads();
    if (threadIdx.x == 0) {
        unsigned gen = g_bar_gen;         // read BEFORE arrival increment
        if (atomicAdd(&g_bar_count, 1u) == GRID_CTAS - 1u) {
            g_bar_count = 0;              // reset for next barrier
            __threadfence();              // order reset + all data before release
            g_bar_gen = gen + 1u;         // release
        } else {
            while (g_bar_gen == gen) { __nanosleep(32); }
        }
    }
    __syncthreads();
}

__device__ __forceinline__ void red_add_v2(float* addr, float x, float y) {
    asm volatile("red.global.add.v2.f32 [%0], {%1, %2};"
                 :: "l"(addr), "f"(x), "f"(y) : "memory");
}
__device__ __forceinline__ void red_add_v4(float* addr, float a, float b, float c, float d) {
    asm volatile("red.global.add.v4.f32 [%0], {%1, %2, %3, %4};"
                 :: "l"(addr), "f"(a), "f"(b), "f"(c), "f"(d) : "memory");
}

// ---------------------------------------------------------------------------
// Overlap stencil — matches reference _overlap_terms exactly:
//   il = clip(floor(lo/BS), 0, NB-1); idx = il + k; valid = idx < NB;
//   idx = min(idx, NB-1); b_lo = idx*BS;
//   ov = max(min(hi, b_lo+BS) - max(lo, b_lo), 0); 0 where invalid.
// True division lo/BS so floor matches JAX bit-for-bit at bin boundaries.
// ---------------------------------------------------------------------------
__device__ __forceinline__ void overlap_terms(float lo, float hi,
                                              int idx[KSTEN], float ov[KSTEN]) {
    int il = (int)floorf(lo / BS);
    il = min(max(il, 0), NB - 1);
#pragma unroll
    for (int k = 0; k < KSTEN; k++) {
        int id = il + k;
        bool valid = id < NB;
        id = min(id, NB - 1);
        float b_lo = (float)id * BS;              // exact: id*125/64 fits in 24 bits
        float o = fminf(hi, b_lo + BS) - fmaxf(lo, b_lo);
        o = fmaxf(o, 0.0f);
        idx[k] = id;
        ov[k]  = valid ? o : 0.0f;
    }
}

// Pack the y-stencil (span <= 3 taps) into a 2-aligned 4-slot window.
__device__ __forceinline__ int pack_y(const int iy[KSTEN], const float ovy[KSTEN],
                                      float scale, float v[4], bool& need1) {
    int j0 = iy[0];
    int s  = j0 & 1;
    int a  = j0 - s;
    v[0] = v[1] = v[2] = v[3] = 0.0f;
    float d0 = ovy[0] * scale;
    float d1 = ovy[1] * scale;
    float d2 = ovy[2] * scale;
    if (s == 0) { v[0] = d0; v[1] = d1; v[2] = d2; }
    else        { v[1] = d0; v[2] = d1; v[3] = d2; }
    need1 = (v[2] != 0.0f) || (v[3] != 0.0f);
    return a;
}

// ---------------------------------------------------------------------------
// One persistent kernel, three phases separated by grid barriers.
// Phase bodies are bit-for-bit the R13 kernels (the measured best).
// ---------------------------------------------------------------------------
__global__ void __launch_bounds__(TPB, 6) k_fused(const float* __restrict__ pos,
                                                  const float* __restrict__ nsx,
                                                  const float* __restrict__ nsy,
                                                  const int*   __restrict__ pin_start,
                                                  float* __restrict__ out) {
    const int tid = blockIdx.x * TPB + threadIdx.x;

    // ---- Phase 1: scatter pin density into the bin map -------------------
    for (int i = tid; i < NUM_PHYS; i += NTHREADS) {
        float sx = nsx[i];
        float sy = nsy[i];
        float hx = 0.5f * fmaxf(stretch_c(), sx);
        float hy = 0.5f * fmaxf(stretch_c(), sy);
        float cx = pos[i]             + 0.5f * sx;
        float cy = pos[NUM_NODES + i] + 0.5f * sy;

        float pw = (float)(pin_start[i + 1] - pin_start[i]);
        float density = pw / (4.0f * hx * hy);

        int   ix[KSTEN], iy[KSTEN];
        float ovx[KSTEN], ovy[KSTEN];
        overlap_terms(cx - hx, cx + hx, ix, ovx);
        overlap_terms(cy - hy, cy + hy, iy, ovy);

        float v[4];
        bool need_p1;
        int a = pack_y(iy, ovy, density, v, need_p1);
        bool fuse4 = need_p1 && ((a & 3) == 0);   // 16B-aligned window

#pragma unroll
        for (int kx = 0; kx < KSTEN; kx++) {
            float r = ovx[kx];
            if (r == 0.0f) continue;              // skip zero x-rows
            float* rowp = &g_pin_map[ix[kx] * NB + a];
            if (fuse4) {
                red_add_v4(rowp, r * v[0], r * v[1], r * v[2], r * v[3]);
            } else {
                red_add_v2(rowp, r * v[0], r * v[1]);
                if (need_p1)
                    red_add_v2(rowp + 2, r * v[2], r * v[3]);
            }
        }
    }

    grid_sync();

    // ---- Phase 2: util = clip(pin_map/denom, 1/1.5, 1.5), re-zero pin_map
    for (int i = tid; i < (NB * NB) / 4; i += NTHREADS) {
        float4 p = ((const float4*)g_pin_map)[i];
        float4 u;
        u.x = fminf(fmaxf(p.x / cap_denom(), min_rate()), 1.5f);
        u.y = fminf(fmaxf(p.y / cap_denom(), min_rate()), 1.5f);
        u.z = fminf(fmaxf(p.z / cap_denom(), min_rate()), 1.5f);
        u.w = fminf(fmaxf(p.w / cap_denom(), min_rate()), 1.5f);
        ((float4*)g_util)[i] = u;
        ((float4*)g_pin_map)[i] = make_float4(0.0f, 0.0f, 0.0f, 0.0f);
    }

    grid_sync();

    // ---- Phase 3: per-movable-node weighted gather (R13 form, bit-exact) -
    for (int m = tid; m < NUM_MOVABLE; m += NTHREADS) {
        float x_lo = pos[m];
        float x_hi = x_lo + nsx[m];
        float y_lo = pos[NUM_NODES + m];
        float y_hi = y_lo + nsy[m];

        int   jx[KSTEN], jy[KSTEN];
        float wx[KSTEN], wy[KSTEN];
        overlap_terms(x_lo, x_hi, jx, wx);
        overlap_terms(y_lo, y_hi, jy, wy);

        float v[4];
        bool need_p1;
        int a = pack_y(jy, wy, 1.0f, v, need_p1);

        float acc = 0.0f;
#pragma unroll
        for (int kx = 0; kx < KSTEN; kx++) {
            float wxk = wx[kx];
            if (wxk == 0.0f) continue;            // whole row contributes 0
            const float* rowp = &g_util[jx[kx] * NB + a];
            float2 u0 = *(const float2*)rowp;     // LDG.64, 8B-aligned
            acc += wxk * (v[0] * u0.x + v[1] * u0.y);
            if (need_p1) {
                float2 u1 = *(const float2*)(rowp + 2);
                acc += wxk * (v[2] * u1.x + v[3] * u1.y);
            }
        }
        out[m] = acc;
    }
}

// ---------------------------------------------------------------------------
extern "C" void kernel_launch(void* const* d_in, const int* in_sizes, int n_in,
                              void* d_out, int out_size) {
    const float* pos       = (const float*)d_in[0];   // 2*NUM_NODES
    const float* nsx       = (const float*)d_in[1];   // NUM_NODES
    const float* nsy       = (const float*)d_in[2];   // NUM_NODES
    const int*   pin_start = (const int*)  d_in[3];   // NUM_PHYS+1
    float*       out       = (float*)d_out;           // NUM_MOVABLE

    k_fused<<<GRID_CTAS, TPB>>>(pos, nsx, nsy, pin_start, out);
}

// round 16
// speedup vs baseline: 1.1292x; 1.1292x over previous
#include <cuda_runtime.h>
#include <cuda_bf16.h>
#include <cuda_fp16.h>

// Problem constants (must match reference)
#define NUM_NODES   1200000
#define NUM_PHYS    1000000
#define NUM_MOVABLE 900000
#define NB          512
#define KSTEN       5

// BSX = BSY = 1000/512 = 1.953125 (exact in fp32)
#define BS 1.953125f

// Compile-time double folds, cast to f32 exactly as JAX weak-type promotion does
__device__ __forceinline__ float stretch_c() { return (float)(1.953125 * 1.4142135623730951); }
__device__ __forceinline__ float cap_denom() { return (float)(1.953125 * 1.953125 * 0.05); }
__device__ __forceinline__ float min_rate()  { return (float)(1.0 / 1.5); }

// Scratch (no allocations allowed). pin_map fp32 row-major; util stored FP16
// (util in [2/3, 1.5] -> rel err <= 2^-11 = 4.9e-4, hard-bounded under the
// 1e-3 gate since outputs are positive-weighted combinations of util values).
// 512KB fp16 map also doubles L1 hit rate and makes each y-pair a single
// 4B-aligned LDG.32 (one sector) instead of float2 sector-crossers.
// __device__ globals are zero-init at load; k_util re-zeroes g_pin_map every
// run, so "pin_map == 0 at scatter entry" holds for the correctness call,
// the capture call, and every graph replay.
__device__ __align__(16) float  g_pin_map[NB * NB];
__device__ __align__(16) __half g_util_h[NB * NB];

__device__ __forceinline__ void red_add_v2(float* addr, float x, float y) {
    asm volatile("red.global.add.v2.f32 [%0], {%1, %2};"
                 :: "l"(addr), "f"(x), "f"(y) : "memory");
}
__device__ __forceinline__ void red_add_v4(float* addr, float a, float b, float c, float d) {
    asm volatile("red.global.add.v4.f32 [%0], {%1, %2, %3, %4};"
                 :: "l"(addr), "f"(a), "f"(b), "f"(c), "f"(d) : "memory");
}

// ---------------------------------------------------------------------------
// Overlap stencil — matches reference _overlap_terms exactly:
//   il = clip(floor(lo/BS), 0, NB-1); idx = il + k; valid = idx < NB;
//   idx = min(idx, NB-1); b_lo = idx*BS;
//   ov = max(min(hi, b_lo+BS) - max(lo, b_lo), 0); 0 where invalid.
// True division lo/BS so floor matches JAX bit-for-bit at bin boundaries.
// ---------------------------------------------------------------------------
__device__ __forceinline__ void overlap_terms(float lo, float hi,
                                              int idx[KSTEN], float ov[KSTEN]) {
    int il = (int)floorf(lo / BS);
    il = min(max(il, 0), NB - 1);
#pragma unroll
    for (int k = 0; k < KSTEN; k++) {
        int id = il + k;
        bool valid = id < NB;
        id = min(id, NB - 1);
        float b_lo = (float)id * BS;              // exact: id*125/64 fits in 24 bits
        float o = fminf(hi, b_lo + BS) - fmaxf(lo, b_lo);
        o = fmaxf(o, 0.0f);
        idx[k] = id;
        ov[k]  = valid ? o : 0.0f;
    }
}

// Pack the y-stencil (span <= 3 taps) into a 2-aligned 4-slot window.
// Returns window start a; fills v[0..3]; need1 = slots 2/3 occupied.
__device__ __forceinline__ int pack_y(const int iy[KSTEN], const float ovy[KSTEN],
                                      float scale, float v[4], bool& need1) {
    int j0 = iy[0];
    int s  = j0 & 1;
    int a  = j0 - s;
    v[0] = v[1] = v[2] = v[3] = 0.0f;
    float d0 = ovy[0] * scale;
    float d1 = ovy[1] * scale;
    float d2 = ovy[2] * scale;
    if (s == 0) { v[0] = d0; v[1] = d1; v[2] = d2; }
    else        { v[1] = d0; v[2] = d1; v[3] = d2; }
    need1 = (v[2] != 0.0f) || (v[3] != 0.0f);
    return a;
}

// ---------------------------------------------------------------------------
// Kernel 1: scatter pin density into the bin map. (bit-for-bit the R12/R13
// measured winner — do not touch.)
// ---------------------------------------------------------------------------
__global__ void __launch_bounds__(256) k_scatter(const float* __restrict__ pos,
                                                 const float* __restrict__ nsx,
                                                 const float* __restrict__ nsy,
                                                 const int*   __restrict__ pin_start) {
    int i = blockIdx.x * blockDim.x + threadIdx.x;
    if (i >= NUM_PHYS) return;

    float sx = nsx[i];
    float sy = nsy[i];
    float hx = 0.5f * fmaxf(stretch_c(), sx);
    float hy = 0.5f * fmaxf(stretch_c(), sy);
    float cx = pos[i]             + 0.5f * sx;
    float cy = pos[NUM_NODES + i] + 0.5f * sy;

    float pw = (float)(pin_start[i + 1] - pin_start[i]);
    float density = pw / (4.0f * hx * hy);

    int   ix[KSTEN], iy[KSTEN];
    float ovx[KSTEN], ovy[KSTEN];
    overlap_terms(cx - hx, cx + hx, ix, ovx);
    overlap_terms(cy - hy, cy + hy, iy, ovy);

    float v[4];
    bool need_p1;
    int a = pack_y(iy, ovy, density, v, need_p1);
    bool fuse4 = need_p1 && ((a & 3) == 0);       // 16B-aligned window

#pragma unroll
    for (int kx = 0; kx < KSTEN; kx++) {
        float r = ovx[kx];
        if (r == 0.0f) continue;                  // skip zero x-rows
        float* rowp = &g_pin_map[ix[kx] * NB + a];
        if (fuse4) {
            red_add_v4(rowp, r * v[0], r * v[1], r * v[2], r * v[3]);
        } else {
            red_add_v2(rowp, r * v[0], r * v[1]);
            if (need_p1)
                red_add_v2(rowp + 2, r * v[2], r * v[3]);
        }
    }
}

// ---------------------------------------------------------------------------
// Kernel 2: util = clip(pin_map / (BSX*BSY*cap), 1/1.5, 1.5), stored as FP16
// (round-to-nearest), float4-wide input; re-zero pin_map for the next replay.
// ---------------------------------------------------------------------------
__global__ void __launch_bounds__(256) k_util() {
    int i = blockIdx.x * blockDim.x + threadIdx.x;
    if (i >= (NB * NB) / 4) return;
    float4 p = ((const float4*)g_pin_map)[i];
    float ux = fminf(fmaxf(p.x / cap_denom(), min_rate()), 1.5f);
    float uy = fminf(fmaxf(p.y / cap_denom(), min_rate()), 1.5f);
    float uz = fminf(fmaxf(p.z / cap_denom(), min_rate()), 1.5f);
    float uw = fminf(fmaxf(p.w / cap_denom(), min_rate()), 1.5f);
    __half2 h01 = __floats2half2_rn(ux, uy);
    __half2 h23 = __floats2half2_rn(uz, uw);
    ((__half2*)g_util_h)[2 * i]     = h01;
    ((__half2*)g_util_h)[2 * i + 1] = h23;
    ((float4*)g_pin_map)[i] = make_float4(0.0f, 0.0f, 0.0f, 0.0f);
}

// ---------------------------------------------------------------------------
// Kernel 3: per-movable-node weighted gather of util -> instance pin area.
// R13 structure (branch-free pair loads, the measured best), with util pairs
// now single 4B-aligned __half2 loads (one sector each, higher L1 hit rate).
// Weights stay exact fp32; accumulation order identical to R13.
// ---------------------------------------------------------------------------
__global__ void __launch_bounds__(256) k_gather(const float* __restrict__ pos,
                                                const float* __restrict__ nsx,
                                                const float* __restrict__ nsy,
                                                float* __restrict__ out) {
    int m = blockIdx.x * blockDim.x + threadIdx.x;
    if (m >= NUM_MOVABLE) return;

    float x_lo = pos[m];
    float x_hi = x_lo + nsx[m];
    float y_lo = pos[NUM_NODES + m];
    float y_hi = y_lo + nsy[m];

    int   jx[KSTEN], jy[KSTEN];
    float wx[KSTEN], wy[KSTEN];
    overlap_terms(x_lo, x_hi, jx, wx);
    overlap_terms(y_lo, y_hi, jy, wy);

    float v[4];
    bool need_p1;
    int a = pack_y(jy, wy, 1.0f, v, need_p1);

    float acc = 0.0f;
#pragma unroll
    for (int kx = 0; kx < KSTEN; kx++) {
        float wxk = wx[kx];
        if (wxk == 0.0f) continue;                // whole row contributes 0
        const __half2* rowp = (const __half2*)&g_util_h[jx[kx] * NB + a];  // a even -> 4B aligned
        float2 u0 = __half22float2(rowp[0]);      // LDG.32, one sector
        acc += wxk * (v[0] * u0.x + v[1] * u0.y);
        if (need_p1) {
            float2 u1 = __half22float2(rowp[1]);
            acc += wxk * (v[2] * u1.x + v[3] * u1.y);
        }
    }
    out[m] = acc;
}

// ---------------------------------------------------------------------------
extern "C" void kernel_launch(void* const* d_in, const int* in_sizes, int n_in,
                              void* d_out, int out_size) {
    const float* pos       = (const float*)d_in[0];   // 2*NUM_NODES
    const float* nsx       = (const float*)d_in[1];   // NUM_NODES
    const float* nsy       = (const float*)d_in[2];   // NUM_NODES
    const int*   pin_start = (const int*)  d_in[3];   // NUM_PHYS+1
    float*       out       = (float*)d_out;           // NUM_MOVABLE

    k_scatter<<<(NUM_PHYS + 255) / 256, 256>>>(pos, nsx, nsy, pin_start);
    k_util<<<((NB * NB) / 4 + 255) / 256, 256>>>();
    k_gather<<<(NUM_MOVABLE + 255) / 256, 256>>>(pos, nsx, nsy, out);
}

// round 17
// speedup vs baseline: 1.1858x; 1.0500x over previous
#include <cuda_runtime.h>
#include <cuda_bf16.h>
#include <cuda_fp16.h>

// Problem constants (must match reference)
#define NUM_NODES   1200000
#define NUM_PHYS    1000000
#define NUM_MOVABLE 900000
#define NB          512
#define KSTEN       5

// BSX = BSY = 1000/512 = 1.953125 (exact in fp32)
#define BS 1.953125f

// Compile-time double folds, cast to f32 exactly as JAX weak-type promotion does
__device__ __forceinline__ float stretch_c() { return (float)(1.953125 * 1.4142135623730951); }
__device__ __forceinline__ float cap_denom() { return (float)(1.953125 * 1.953125 * 0.05); }
__device__ __forceinline__ float min_rate()  { return (float)(1.0 / 1.5); }

// Scratch (no allocations allowed). pin_map fp32 row-major; util stored FP16
// (util in [2/3, 1.5] -> per-value rel err <= 2^-11 = 4.9e-4, hard-bounded
// under the 1e-3 gate since outputs are positive-weighted combinations;
// measured rel_err 1.6e-7). __device__ globals are zero-init at load; k_util
// re-zeroes g_pin_map every run, so "pin_map == 0 at scatter entry" holds for
// the correctness call, the capture call, and every graph replay.
__device__ __align__(16) float  g_pin_map[NB * NB];
__device__ __align__(16) __half g_util_h[NB * NB];

__device__ __forceinline__ void red_add_v2(float* addr, float x, float y) {
    asm volatile("red.global.add.v2.f32 [%0], {%1, %2};"
                 :: "l"(addr), "f"(x), "f"(y) : "memory");
}
__device__ __forceinline__ void red_add_v4(float* addr, float a, float b, float c, float d) {
    asm volatile("red.global.add.v4.f32 [%0], {%1, %2, %3, %4};"
                 :: "l"(addr), "f"(a), "f"(b), "f"(c), "f"(d) : "memory");
}

// ---------------------------------------------------------------------------
// Overlap stencil — matches reference _overlap_terms exactly:
//   il = clip(floor(lo/BS), 0, NB-1); idx = il + k; valid = idx < NB;
//   idx = min(idx, NB-1); b_lo = idx*BS;
//   ov = max(min(hi, b_lo+BS) - max(lo, b_lo), 0); 0 where invalid.
// True division lo/BS so floor matches JAX bit-for-bit at bin boundaries.
// ---------------------------------------------------------------------------
__device__ __forceinline__ void overlap_terms(float lo, float hi,
                                              int idx[KSTEN], float ov[KSTEN]) {
    int il = (int)floorf(lo / BS);
    il = min(max(il, 0), NB - 1);
#pragma unroll
    for (int k = 0; k < KSTEN; k++) {
        int id = il + k;
        bool valid = id < NB;
        id = min(id, NB - 1);
        float b_lo = (float)id * BS;              // exact: id*125/64 fits in 24 bits
        float o = fminf(hi, b_lo + BS) - fmaxf(lo, b_lo);
        o = fmaxf(o, 0.0f);
        idx[k] = id;
        ov[k]  = valid ? o : 0.0f;
    }
}

// Pack the y-stencil (span <= 3 taps) into a 2-aligned 4-slot window.
// Returns window start a; fills v[0..3]; need1 = slots 2/3 occupied.
__device__ __forceinline__ int pack_y(const int iy[KSTEN], const float ovy[KSTEN],
                                      float scale, float v[4], bool& need1) {
    int j0 = iy[0];
    int s  = j0 & 1;
    int a  = j0 - s;
    v[0] = v[1] = v[2] = v[3] = 0.0f;
    float d0 = ovy[0] * scale;
    float d1 = ovy[1] * scale;
    float d2 = ovy[2] * scale;
    if (s == 0) { v[0] = d0; v[1] = d1; v[2] = d2; }
    else        { v[1] = d0; v[2] = d1; v[3] = d2; }
    need1 = (v[2] != 0.0f) || (v[3] != 0.0f);
    return a;
}

// ---------------------------------------------------------------------------
// Kernel 1: scatter pin density into the bin map. (bit-for-bit the R12/R16
// measured winner — do not touch.) PDL primary: implicit trigger at finish.
// ---------------------------------------------------------------------------
__global__ void __launch_bounds__(256) k_scatter(const float* __restrict__ pos,
                                                 const float* __restrict__ nsx,
                                                 const float* __restrict__ nsy,
                                                 const int*   __restrict__ pin_start) {
    int i = blockIdx.x * blockDim.x + threadIdx.x;
    if (i >= NUM_PHYS) return;

    float sx = nsx[i];
    float sy = nsy[i];
    float hx = 0.5f * fmaxf(stretch_c(), sx);
    float hy = 0.5f * fmaxf(stretch_c(), sy);
    float cx = pos[i]             + 0.5f * sx;
    float cy = pos[NUM_NODES + i] + 0.5f * sy;

    float pw = (float)(pin_start[i + 1] - pin_start[i]);
    float density = pw / (4.0f * hx * hy);

    int   ix[KSTEN], iy[KSTEN];
    float ovx[KSTEN], ovy[KSTEN];
    overlap_terms(cx - hx, cx + hx, ix, ovx);
    overlap_terms(cy - hy, cy + hy, iy, ovy);

    float v[4];
    bool need_p1;
    int a = pack_y(iy, ovy, density, v, need_p1);
    bool fuse4 = need_p1 && ((a & 3) == 0);       // 16B-aligned window

#pragma unroll
    for (int kx = 0; kx < KSTEN; kx++) {
        float r = ovx[kx];
        if (r == 0.0f) continue;                  // skip zero x-rows
        float* rowp = &g_pin_map[ix[kx] * NB + a];
        if (fuse4) {
            red_add_v4(rowp, r * v[0], r * v[1], r * v[2], r * v[3]);
        } else {
            red_add_v2(rowp, r * v[0], r * v[1]);
            if (need_p1)
                red_add_v2(rowp + 2, r * v[2], r * v[3]);
        }
    }
}

// ---------------------------------------------------------------------------
// Kernel 2: util = clip(pin_map / (BSX*BSY*cap), 1/1.5, 1.5) -> FP16 store;
// re-zero pin_map. PDL secondary: launches under the scatter's tail, waits
// for scatter's memory before reading pin_map.
// ---------------------------------------------------------------------------
__global__ void __launch_bounds__(256) k_util() {
    cudaGridDependencySynchronize();              // scatter REDs visible after this
    int i = blockIdx.x * blockDim.x + threadIdx.x;
    if (i >= (NB * NB) / 4) return;
    float4 p = ((const float4*)g_pin_map)[i];
    float ux = fminf(fmaxf(p.x / cap_denom(), min_rate()), 1.5f);
    float uy = fminf(fmaxf(p.y / cap_denom(), min_rate()), 1.5f);
    float uz = fminf(fmaxf(p.z / cap_denom(), min_rate()), 1.5f);
    float uw = fminf(fmaxf(p.w / cap_denom(), min_rate()), 1.5f);
    ((__half2*)g_util_h)[2 * i]     = __floats2half2_rn(ux, uy);
    ((__half2*)g_util_h)[2 * i + 1] = __floats2half2_rn(uz, uw);
    ((float4*)g_pin_map)[i] = make_float4(0.0f, 0.0f, 0.0f, 0.0f);
}

// ---------------------------------------------------------------------------
// Kernel 3: per-movable-node weighted gather. PDL secondary: the entire
// prologue (DRAM loads of pos/nsx/nsy + both stencils + y-pack) is
// independent of g_util_h and runs concurrently with k_util and the scatter
// tail; the dependency sync sits immediately before the first util read.
// Arithmetic identical to R16 (measured best).
// ---------------------------------------------------------------------------
__global__ void __launch_bounds__(256) k_gather(const float* __restrict__ pos,
                                                const float* __restrict__ nsx,
                                                const float* __restrict__ nsy,
                                                float* __restrict__ out) {
    int m = blockIdx.x * blockDim.x + threadIdx.x;
    bool active = (m < NUM_MOVABLE);
    int mm = active ? m : 0;

    // ---- independent prologue (overlaps predecessor kernels) ----
    float x_lo = pos[mm];
    float x_hi = x_lo + nsx[mm];
    float y_lo = pos[NUM_NODES + mm];
    float y_hi = y_lo + nsy[mm];

    int   jx[KSTEN], jy[KSTEN];
    float wx[KSTEN], wy[KSTEN];
    overlap_terms(x_lo, x_hi, jx, wx);
    overlap_terms(y_lo, y_hi, jy, wy);

    float v[4];
    bool need_p1;
    int a = pack_y(jy, wy, 1.0f, v, need_p1);

    // ---- dependent part: util map reads ----
    cudaGridDependencySynchronize();              // k_util stores visible after this

    float acc = 0.0f;
#pragma unroll
    for (int kx = 0; kx < KSTEN; kx++) {
        float wxk = wx[kx];
        if (wxk == 0.0f) continue;                // whole row contributes 0
        const __half2* rowp = (const __half2*)&g_util_h[jx[kx] * NB + a];  // a even -> 4B aligned
        float2 u0 = __half22float2(rowp[0]);      // LDG.32, one sector
        acc += wxk * (v[0] * u0.x + v[1] * u0.y);
        if (need_p1) {
            float2 u1 = __half22float2(rowp[1]);
            acc += wxk * (v[2] * u1.x + v[3] * u1.y);
        }
    }
    if (active) out[m] = acc;
}

// ---------------------------------------------------------------------------
extern "C" void kernel_launch(void* const* d_in, const int* in_sizes, int n_in,
                              void* d_out, int out_size) {
    const float* pos       = (const float*)d_in[0];   // 2*NUM_NODES
    const float* nsx       = (const float*)d_in[1];   // NUM_NODES
    const float* nsy       = (const float*)d_in[2];   // NUM_NODES
    const int*   pin_start = (const int*)  d_in[3];   // NUM_PHYS+1
    float*       out       = (float*)d_out;           // NUM_MOVABLE

    // Primary: normal launch (implicit programmatic trigger at completion).
    k_scatter<<<(NUM_PHYS + 255) / 256, 256>>>(pos, nsx, nsy, pin_start);

    // Secondaries: programmatic stream serialization (PDL). Launch overlaps
    // the predecessor; in-kernel cudaGridDependencySynchronize() enforces the
    // data dependency. Graph-capturable (programmatic edges) on CUDA 12+.
    cudaLaunchAttribute pdl_attr[1];
    pdl_attr[0].id = cudaLaunchAttributeProgrammaticStreamSerialization;
    pdl_attr[0].val.programmaticStreamSerializationAllowed = 1;

    {
        cudaLaunchConfig_t cfg = {};
        cfg.gridDim  = dim3(((NB * NB) / 4 + 255) / 256);
        cfg.blockDim = dim3(256);
        cfg.dynamicSmemBytes = 0;
        cfg.stream = 0;                            // legacy default (capture) stream
        cfg.attrs = pdl_attr;
        cfg.numAttrs = 1;
        cudaLaunchKernelEx(&cfg, k_util);
    }
    {
        cudaLaunchConfig_t cfg = {};
        cfg.gridDim  = dim3((NUM_MOVABLE + 255) / 256);
        cfg.blockDim = dim3(256);
        cfg.dynamicSmemBytes = 0;
        cfg.stream = 0;
        cfg.attrs = pdl_attr;
        cfg.numAttrs = 1;
        cudaLaunchKernelEx(&cfg, k_gather, pos, nsx, nsy, out);
    }
}